// round 7
// baseline (speedup 1.0000x reference)
#include <cuda_runtime.h>
#include <math.h>

#define NN 50000
#define EE 800000
#define HH 128
#define GG 50
#define FF 128
#define BB 256

#define TILE 128          // rows (nodes or edges) per block-tile
#define PAD 132           // smem row stride (multiple of 4 for float4 loads)
#define NT 1024           // threads per block (2 K-groups of 512)
#define NB_NODE ((NN + TILE - 1) / TILE)   // 391
#define NT_EDGE (EE / TILE)                // 6250
#define EDGE_BLOCKS 148

// ---------------- scratch (device globals; 16B-aligned for float4 access) -----
__device__ __align__(16) float g_h2[NN * HH];
__device__ __align__(16) float g_xf[NN * FF];
__device__ __align__(16) float g_agg[NN * FF];
__device__ __align__(16) float g_hbuf[NN * HH];
__device__ float g_state2[BB * 2];
__device__ float g_pool[BB];
__device__ float g_cnt[BB];
__device__ int   g_tile_ctr;

// shifted softplus: log(1+e^x) - log(2)
__device__ __forceinline__ float ssp(float x) {
    float sp = (x > 15.0f) ? x : log1pf(__expf(x));
    return sp - 0.69314718055994531f;
}

// 8t x 4f register-tiled inner product, vectorized activation loads.
// sW: [k][f] k-major (stride 128), sX: [k][t] k-major (stride LD, LD%4==0).
// Activation loads are warp-uniform (t0 fixed per warp) => broadcast, conflict-free.
template <int K, int LD>
__device__ __forceinline__ void gemm_tile_v(const float* __restrict__ sW,
                                            const float* __restrict__ sX,
                                            int f0, int t0, float4 acc[8]) {
    const float* xp = sX + t0;
    const float* wp = sW + f0;
#pragma unroll 4
    for (int k = 0; k < K; k++) {
        float4 w4 = *(const float4*)wp;
        float4 a0 = *(const float4*)xp;
        float4 a1 = *(const float4*)(xp + 4);
        acc[0].x = fmaf(a0.x, w4.x, acc[0].x);
        acc[0].y = fmaf(a0.x, w4.y, acc[0].y);
        acc[0].z = fmaf(a0.x, w4.z, acc[0].z);
        acc[0].w = fmaf(a0.x, w4.w, acc[0].w);
        acc[1].x = fmaf(a0.y, w4.x, acc[1].x);
        acc[1].y = fmaf(a0.y, w4.y, acc[1].y);
        acc[1].z = fmaf(a0.y, w4.z, acc[1].z);
        acc[1].w = fmaf(a0.y, w4.w, acc[1].w);
        acc[2].x = fmaf(a0.z, w4.x, acc[2].x);
        acc[2].y = fmaf(a0.z, w4.y, acc[2].y);
        acc[2].z = fmaf(a0.z, w4.z, acc[2].z);
        acc[2].w = fmaf(a0.z, w4.w, acc[2].w);
        acc[3].x = fmaf(a0.w, w4.x, acc[3].x);
        acc[3].y = fmaf(a0.w, w4.y, acc[3].y);
        acc[3].z = fmaf(a0.w, w4.z, acc[3].z);
        acc[3].w = fmaf(a0.w, w4.w, acc[3].w);
        acc[4].x = fmaf(a1.x, w4.x, acc[4].x);
        acc[4].y = fmaf(a1.x, w4.y, acc[4].y);
        acc[4].z = fmaf(a1.x, w4.z, acc[4].z);
        acc[4].w = fmaf(a1.x, w4.w, acc[4].w);
        acc[5].x = fmaf(a1.y, w4.x, acc[5].x);
        acc[5].y = fmaf(a1.y, w4.y, acc[5].y);
        acc[5].z = fmaf(a1.y, w4.z, acc[5].z);
        acc[5].w = fmaf(a1.y, w4.w, acc[5].w);
        acc[6].x = fmaf(a1.z, w4.x, acc[6].x);
        acc[6].y = fmaf(a1.z, w4.y, acc[6].y);
        acc[6].z = fmaf(a1.z, w4.z, acc[6].z);
        acc[6].w = fmaf(a1.z, w4.w, acc[6].w);
        acc[7].x = fmaf(a1.w, w4.x, acc[7].x);
        acc[7].y = fmaf(a1.w, w4.y, acc[7].y);
        acc[7].z = fmaf(a1.w, w4.z, acc[7].z);
        acc[7].w = fmaf(a1.w, w4.w, acc[7].w);
        xp += LD;
        wp += 128;
    }
}

// ---------------- small helper kernels ----------------------------------------
__global__ void k_init(const float* __restrict__ state_attr) {
    int b = blockIdx.x * blockDim.x + threadIdx.x;
    if (b < BB) {
        g_cnt[b] = 0.0f;
        g_pool[b] = 0.0f;
        g_state2[2 * b]     = state_attr[2 * b];
        g_state2[2 * b + 1] = state_attr[2 * b + 1];
    }
}

__global__ void k_count(const int* __restrict__ batch) {
    int n = blockIdx.x * blockDim.x + threadIdx.x;
    if (n < NN) atomicAdd(&g_cnt[batch[n]], 1.0f);
}

__global__ void k_state() {
    int b = threadIdx.x;
    if (b < BB) {
        float s = g_pool[b] / fmaxf(g_cnt[b], 1.0f);
        g_state2[2 * b]     = s;
        g_state2[2 * b + 1] = s;
        g_pool[b] = 0.0f;
    }
}

__global__ void k_reset() {
    if (threadIdx.x == 0) g_tile_ctr = 0;
}

// ---------------- node GEMM kernel (4 modes), 1024 threads, K-split -----------
// MODE 0: h2 = [sa,h] @ lin1_w^T + b   (X = h input), writes g_h2, zeroes g_agg
// MODE 1: xf = g_h2 @ conv_lin1_w^T,   writes g_xf
// MODE 2: h  = g_h2 + ssp(g_agg @ conv_lin2_w^T + b), writes g_hbuf (+pool)
// MODE 3: out = g_hbuf @ out_w^T + b,  writes Yext (d_out)
#define NODE_SMEM_FLOATS (17152 + TILE * PAD)
#define NODE_SMEM_BYTES  (NODE_SMEM_FLOATS * 4)

template <int MODE>
__global__ void __launch_bounds__(NT, 1)
node_gemm(const float* __restrict__ Xext, const float* __restrict__ W,
          const float* __restrict__ bias, const int* __restrict__ batch,
          float* __restrict__ Yext, int do_pool) {
    extern __shared__ float sm[];
    float* sW    = sm;            // 16384
    float* sb    = sm + 16384;    // 128
    float* sw0   = sm + 16512;    // 128
    float* sw1   = sm + 16640;    // 128
    float* spool = sm + 16768;    // 128
    float* ssa0  = sm + 16896;    // 128
    float* ssa1  = sm + 17024;    // 128
    float* sX    = sm + 17152;    // 128*PAD (doubles as reduction staging)

    const int tid = threadIdx.x;
    const int n0  = blockIdx.x * TILE;

    const float* X;
    float* Y;
    float* aux = 0;
    if (MODE == 0)      { X = Xext ? Xext : g_hbuf; Y = g_h2;   aux = g_agg; }
    else if (MODE == 1) { X = g_h2;                 Y = g_xf; }
    else if (MODE == 2) { X = g_agg;                Y = g_hbuf; aux = g_h2; }
    else                { X = g_hbuf;               Y = Yext; }

    constexpr int ldw  = (MODE == 0) ? 130 : 128;
    constexpr int woff = (MODE == 0) ? 2 : 0;

    for (int i = tid; i < 128 * 128; i += NT) {
        int f = i >> 7, k = i & 127;
        sW[k * 128 + f] = W[f * ldw + woff + k];
    }
    if (tid < 128) {
        sb[tid] = bias ? bias[tid] : 0.0f;
        spool[tid] = 0.0f;
        if (MODE == 0) {
            sw0[tid] = W[tid * 130];
            sw1[tid] = W[tid * 130 + 1];
            float a0 = 0.0f, a1 = 0.0f;
            int n = n0 + tid;
            if (n < NN) {
                int b = batch[n];
                a0 = g_state2[2 * b];
                a1 = g_state2[2 * b + 1];
            }
            ssa0[tid] = a0;
            ssa1[tid] = a1;
        }
    }
    for (int i = tid; i < TILE * 128; i += NT) {
        int t = i >> 7, k = i & 127;
        int n = n0 + t;
        sX[k * PAD + t] = (n < NN) ? X[(size_t)n * 128 + k] : 0.0f;
    }
    __syncthreads();

    const int grp = tid >> 9;               // K-group: 0 or 1
    const int f0  = (tid & 31) * 4;
    const int t0  = ((tid >> 5) & 15) * 8;

    float4 acc[8];
    if (grp == 0) {
        float4 b4 = *(const float4*)&sb[f0];
#pragma unroll
        for (int j = 0; j < 8; j++)
            acc[j] = (MODE == 1) ? make_float4(0.f, 0.f, 0.f, 0.f) : b4;
        if (MODE == 0) {
            float4 w04 = *(const float4*)&sw0[f0];
            float4 w14 = *(const float4*)&sw1[f0];
#pragma unroll
            for (int j = 0; j < 8; j++) {
                float a0 = ssa0[t0 + j], a1 = ssa1[t0 + j];
                acc[j].x += a0 * w04.x + a1 * w14.x;
                acc[j].y += a0 * w04.y + a1 * w14.y;
                acc[j].z += a0 * w04.z + a1 * w14.z;
                acc[j].w += a0 * w04.w + a1 * w14.w;
            }
        }
    } else {
#pragma unroll
        for (int j = 0; j < 8; j++) acc[j] = make_float4(0.f, 0.f, 0.f, 0.f);
    }

    // each group does half of K
    gemm_tile_v<64, PAD>(sW + (size_t)grp * 64 * 128, sX + grp * 64 * PAD,
                         f0, t0, acc);

    // reduce group1 -> group0 through sX (dead after GEMM reads)
    __syncthreads();
    if (grp == 1) {
#pragma unroll
        for (int j = 0; j < 8; j++)
            *(float4*)&sX[(t0 + j) * 128 + f0] = acc[j];
    }
    __syncthreads();

    if (grp == 0) {
#pragma unroll
        for (int j = 0; j < 8; j++) {
            float4 p = *(const float4*)&sX[(t0 + j) * 128 + f0];
            acc[j].x += p.x;
            acc[j].y += p.y;
            acc[j].z += p.z;
            acc[j].w += p.w;
            int t = t0 + j;
            int n = n0 + t;
            if (n >= NN) continue;
            size_t off = (size_t)n * 128 + f0;
            if (MODE == 0) {
                *(float4*)&Y[off]   = acc[j];
                *(float4*)&aux[off] = make_float4(0.f, 0.f, 0.f, 0.f);
            } else if (MODE == 2) {
                float4 h2v = *(const float4*)&aux[off];
                float4 v;
                v.x = h2v.x + ssp(acc[j].x);
                v.y = h2v.y + ssp(acc[j].y);
                v.z = h2v.z + ssp(acc[j].z);
                v.w = h2v.w + ssp(acc[j].w);
                *(float4*)&Y[off] = v;
                if (do_pool) atomicAdd(&spool[t], v.x + v.y + v.z + v.w);
            } else {
                *(float4*)&Y[off] = acc[j];
            }
        }
    }

    if (MODE == 2 && do_pool) {
        __syncthreads();
        if (tid < TILE) {
            int n = n0 + tid;
            if (n < NN) atomicAdd(&g_pool[batch[n]], spool[tid]);
        }
    }
}

// ---------------- fused edge kernel (1024 threads, K-split) --------------------
// Per 128-edge tile: z = ssp(ea @ W1^T + b1); eh = z @ W2^T + b2;
// msg = eh * C * xf[src]; vector-red into agg[dst]. Persistent + work stealing.
// Stage-2 K-split partials scatter directly (multiply distributes over sum).
#define EDGE_SMEM_FLOATS (30024 + 128 * PAD)
#define EDGE_SMEM_BYTES  (EDGE_SMEM_FLOATS * 4)

__global__ void __launch_bounds__(NT, 1)
edge_kernel(const float* __restrict__ ea, const float* __restrict__ ew,
            const int* __restrict__ eidx,
            const float* __restrict__ W1, const float* __restrict__ b1,
            const float* __restrict__ W2, const float* __restrict__ b2) {
    extern __shared__ float sm[];
    float* sW1 = sm;                   // 50*128 = 6400
    float* sb1 = sm + 6400;            // 128
    float* sW2 = sm + 6528;            // 16384
    float* sb2 = sm + 22912;           // 128
    float* sC  = sm + 23040;           // 128
    int* sSrc  = (int*)(sm + 23168);   // 128
    int* sDst  = (int*)(sm + 23296);   // 128
    float* sEA = sm + 23424;           // 50*PAD = 6600
    float* sZ  = sm + 30024;           // 128*PAD (also stage-1 reduction staging)
    __shared__ int s_tile;

    const int tid = threadIdx.x;

    for (int i = tid; i < 128 * 50; i += NT) {
        int f = i / 50, k = i - f * 50;
        sW1[k * 128 + f] = W1[i];
    }
    for (int i = tid; i < 128 * 128; i += NT) {
        int f = i >> 7, k = i & 127;
        sW2[k * 128 + f] = W2[i];
    }
    if (tid < 128) {
        sb1[tid] = b1[tid];
        sb2[tid] = b2[tid];
    }

    const int grp = tid >> 9;               // K-group: 0 or 1
    const int f0  = (tid & 31) * 4;
    const int t0  = ((tid >> 5) & 15) * 8;

    for (;;) {
        __syncthreads();
        if (tid == 0) s_tile = atomicAdd(&g_tile_ctr, 1);
        __syncthreads();
        const int tile = s_tile;
        if (tile >= NT_EDGE) break;
        const int e0 = tile * TILE;

        for (int i = tid; i < TILE * 50; i += NT) {
            int t = i / 50, k = i - t * 50;
            sEA[k * PAD + t] = ea[(size_t)(e0 + t) * 50 + k];
        }
        if (tid < TILE) {
            int e = e0 + tid;
            sC[tid]  = 0.5f * (__cosf(ew[e] * 0.62831853071795864769f) + 1.0f);
            sSrc[tid] = eidx[e];
            sDst[tid] = eidx[EE + e];
        }
        __syncthreads();

        // stage 1: z = ssp(ea @ W1^T + b1). K=50 split 25/25; group1 stages
        // pre-activation partial into sZ, group0 combines + ssp, writes sZ [k][t].
        {
            float4 acc[8];
            if (grp == 0) {
                float4 b4 = *(const float4*)&sb1[f0];
#pragma unroll
                for (int j = 0; j < 8; j++) acc[j] = b4;
            } else {
#pragma unroll
                for (int j = 0; j < 8; j++) acc[j] = make_float4(0.f, 0.f, 0.f, 0.f);
            }
            gemm_tile_v<25, PAD>(sW1 + (size_t)grp * 25 * 128,
                                 sEA + grp * 25 * PAD, f0, t0, acc);
            if (grp == 1) {
#pragma unroll
                for (int i = 0; i < 4; i++) {
                    const float* a = (const float*)acc;
                    float4 lo, hi;
                    lo.x = a[0 * 4 + i]; lo.y = a[1 * 4 + i];
                    lo.z = a[2 * 4 + i]; lo.w = a[3 * 4 + i];
                    hi.x = a[4 * 4 + i]; hi.y = a[5 * 4 + i];
                    hi.z = a[6 * 4 + i]; hi.w = a[7 * 4 + i];
                    *(float4*)&sZ[(f0 + i) * PAD + t0]     = lo;
                    *(float4*)&sZ[(f0 + i) * PAD + t0 + 4] = hi;
                }
            }
            __syncthreads();
            if (grp == 0) {
#pragma unroll
                for (int i = 0; i < 4; i++) {
                    const float* a = (const float*)acc;
                    float4 lo = *(const float4*)&sZ[(f0 + i) * PAD + t0];
                    float4 hi = *(const float4*)&sZ[(f0 + i) * PAD + t0 + 4];
                    lo.x = ssp(lo.x + a[0 * 4 + i]);
                    lo.y = ssp(lo.y + a[1 * 4 + i]);
                    lo.z = ssp(lo.z + a[2 * 4 + i]);
                    lo.w = ssp(lo.w + a[3 * 4 + i]);
                    hi.x = ssp(hi.x + a[4 * 4 + i]);
                    hi.y = ssp(hi.y + a[5 * 4 + i]);
                    hi.z = ssp(hi.z + a[6 * 4 + i]);
                    hi.w = ssp(hi.w + a[7 * 4 + i]);
                    *(float4*)&sZ[(f0 + i) * PAD + t0]     = lo;
                    *(float4*)&sZ[(f0 + i) * PAD + t0 + 4] = hi;
                }
            }
        }
        __syncthreads();

        // stage 2: eh = z @ W2^T + b2 (K=128 split 64/64); each group scatters
        // its partial directly: msg_partial = p * c * xf[src] -> red to agg[dst].
        {
            float4 acc[8];
            if (grp == 0) {
                float4 b4 = *(const float4*)&sb2[f0];
#pragma unroll
                for (int j = 0; j < 8; j++) acc[j] = b4;
            } else {
#pragma unroll
                for (int j = 0; j < 8; j++) acc[j] = make_float4(0.f, 0.f, 0.f, 0.f);
            }
            gemm_tile_v<64, PAD>(sW2 + (size_t)grp * 64 * 128,
                                 sZ + grp * 64 * PAD, f0, t0, acc);
#pragma unroll
            for (int j = 0; j < 8; j++) {
                int t = t0 + j;
                float c = sC[t];
                int s = sSrc[t], d = sDst[t];
                float4 x4 = *(const float4*)&g_xf[(size_t)s * 128 + f0];
                float4 m;
                m.x = acc[j].x * c * x4.x;
                m.y = acc[j].y * c * x4.y;
                m.z = acc[j].z * c * x4.z;
                m.w = acc[j].w * c * x4.w;
                float* ap = g_agg + (size_t)d * 128 + f0;
                asm volatile("red.global.add.v4.f32 [%0], {%1, %2, %3, %4};"
                             :: "l"(ap), "f"(m.x), "f"(m.y), "f"(m.z), "f"(m.w)
                             : "memory");
            }
        }
    }
}

// ---------------- launcher -----------------------------------------------------
extern "C" void kernel_launch(void* const* d_in, const int* in_sizes, int n_in,
                              void* d_out, int out_size) {
    const float* h      = (const float*)d_in[0];
    const float* ew     = (const float*)d_in[1];
    const float* ea     = (const float*)d_in[2];
    const float* st     = (const float*)d_in[3];
    const float* lin1w  = (const float*)d_in[4];
    const float* lin1b  = (const float*)d_in[5];
    const float* mw1    = (const float*)d_in[6];
    const float* mb1    = (const float*)d_in[7];
    const float* mw2    = (const float*)d_in[8];
    const float* mb2    = (const float*)d_in[9];
    const float* cl1    = (const float*)d_in[10];
    const float* cl2    = (const float*)d_in[11];
    const float* cl2b   = (const float*)d_in[12];
    const float* outw   = (const float*)d_in[13];
    const float* outb   = (const float*)d_in[14];
    const int* eidx  = (const int*)d_in[15];
    const int* batch = (const int*)d_in[16];
    float* out = (float*)d_out;

    cudaFuncSetAttribute(node_gemm<0>, cudaFuncAttributeMaxDynamicSharedMemorySize, NODE_SMEM_BYTES);
    cudaFuncSetAttribute(node_gemm<1>, cudaFuncAttributeMaxDynamicSharedMemorySize, NODE_SMEM_BYTES);
    cudaFuncSetAttribute(node_gemm<2>, cudaFuncAttributeMaxDynamicSharedMemorySize, NODE_SMEM_BYTES);
    cudaFuncSetAttribute(node_gemm<3>, cudaFuncAttributeMaxDynamicSharedMemorySize, NODE_SMEM_BYTES);
    cudaFuncSetAttribute(edge_kernel,  cudaFuncAttributeMaxDynamicSharedMemorySize, EDGE_SMEM_BYTES);

    k_init<<<1, 256>>>(st);
    k_count<<<(NN + 255) / 256, 256>>>(batch);

    for (int i = 0; i < 2; i++) {
        const float* hin = (i == 0) ? h : (const float*)0;  // null => g_hbuf
        node_gemm<0><<<NB_NODE, NT, NODE_SMEM_BYTES>>>(
            hin, lin1w + i * 128 * 130, lin1b + i * 128, batch, (float*)0, 0);
        node_gemm<1><<<NB_NODE, NT, NODE_SMEM_BYTES>>>(
            (const float*)0, cl1 + i * 128 * 128, (const float*)0, batch, (float*)0, 0);
        k_reset<<<1, 32>>>();
        edge_kernel<<<EDGE_BLOCKS, NT, EDGE_SMEM_BYTES>>>(
            ea, ew, eidx, mw1 + i * 128 * 50, mb1 + i * 128,
            mw2 + i * 128 * 128, mb2 + i * 128);
        node_gemm<2><<<NB_NODE, NT, NODE_SMEM_BYTES>>>(
            (const float*)0, cl2 + i * 128 * 128, cl2b + i * 128, batch, (float*)0,
            (i == 0) ? 1 : 0);
        if (i == 0) k_state<<<1, 256>>>();
    }
    node_gemm<3><<<NB_NODE, NT, NODE_SMEM_BYTES>>>(
        (const float*)0, outw, outb, batch, out, 0);
}

// round 8
// speedup vs baseline: 1.1984x; 1.1984x over previous
#include <cuda_runtime.h>
#include <math.h>

#define NN 50000
#define EE 800000
#define HH 128
#define GG 50
#define FF 128
#define BB 256

#define TILE 128          // rows (nodes or edges) per block-tile
#define PAD 132           // smem row stride (multiple of 4 for 16B-aligned loads)
#define NTHREADS 512
#define NB_NODE ((NN + TILE - 1) / TILE)   // 391
#define NT_EDGE (EE / TILE)                // 6250
#define EDGE_BLOCKS 148

typedef unsigned long long u64;

// ---------------- scratch (device globals; 16B-aligned for float4 access) -----
__device__ __align__(16) float g_h2[NN * HH];
__device__ __align__(16) float g_xf[NN * FF];
__device__ __align__(16) float g_agg[NN * FF];
__device__ __align__(16) float g_hbuf[NN * HH];
__device__ float g_state2[BB * 2];
__device__ float g_pool[BB];
__device__ float g_cnt[BB];
__device__ int   g_tile_ctr;

// shifted softplus: log(1+e^x) - log(2)
__device__ __forceinline__ float ssp(float x) {
    float sp = (x > 15.0f) ? x : log1pf(__expf(x));
    return sp - 0.69314718055994531f;
}

// ---- packed fp32x2 helpers (Blackwell dual-rate fp32 path) --------------------
__device__ __forceinline__ u64 pk2(float v) {
    u64 r;
    unsigned u = __float_as_uint(v);
    asm("mov.b64 %0, {%1, %1};" : "=l"(r) : "r"(u));
    return r;
}
__device__ __forceinline__ float2 upk(u64 p) {
    unsigned lo, hi;
    asm("mov.b64 {%0, %1}, %2;" : "=r"(lo), "=r"(hi) : "l"(p));
    return make_float2(__uint_as_float(lo), __uint_as_float(hi));
}
#define FMA2(acc, a, b) \
    asm("fma.rn.f32x2 %0, %1, %2, %0;" : "+l"(acc) : "l"(a), "l"(b))

// 8t x 4f register tile, t-pair packed: acc[tp*4+fi] holds (t0+2tp, t0+2tp+1)
// for feature f0+fi. sW: [k][f] stride 128; sX: [k][t] stride LD (16B aligned).
// Activation LDS.128 yields two f32x2 pairs directly; weights dup-packed (4 MOV/k).
template <int K, int LD>
__device__ __forceinline__ void gemm_tile_p(const float* __restrict__ sW,
                                            const float* __restrict__ sX,
                                            int f0, int t0, u64 acc[16]) {
    const float* xp = sX + t0;
    const float* wp = sW + f0;
#pragma unroll 4
    for (int k = 0; k < K; k++) {
        float4 w4 = *(const float4*)wp;
        ulonglong2 A0 = *(const ulonglong2*)xp;        // pairs (t0,t0+1),(t0+2,t0+3)
        ulonglong2 A1 = *(const ulonglong2*)(xp + 4);  // pairs (t0+4,..),(t0+6,..)
        u64 wd0 = pk2(w4.x), wd1 = pk2(w4.y), wd2 = pk2(w4.z), wd3 = pk2(w4.w);
        FMA2(acc[0],  A0.x, wd0); FMA2(acc[1],  A0.x, wd1);
        FMA2(acc[2],  A0.x, wd2); FMA2(acc[3],  A0.x, wd3);
        FMA2(acc[4],  A0.y, wd0); FMA2(acc[5],  A0.y, wd1);
        FMA2(acc[6],  A0.y, wd2); FMA2(acc[7],  A0.y, wd3);
        FMA2(acc[8],  A1.x, wd0); FMA2(acc[9],  A1.x, wd1);
        FMA2(acc[10], A1.x, wd2); FMA2(acc[11], A1.x, wd3);
        FMA2(acc[12], A1.y, wd0); FMA2(acc[13], A1.y, wd1);
        FMA2(acc[14], A1.y, wd2); FMA2(acc[15], A1.y, wd3);
        xp += LD;
        wp += 128;
    }
}

// ---------------- small helper kernels ----------------------------------------
__global__ void k_init(const float* __restrict__ state_attr) {
    int b = blockIdx.x * blockDim.x + threadIdx.x;
    if (b < BB) {
        g_cnt[b] = 0.0f;
        g_pool[b] = 0.0f;
        g_state2[2 * b]     = state_attr[2 * b];
        g_state2[2 * b + 1] = state_attr[2 * b + 1];
    }
}

__global__ void k_count(const int* __restrict__ batch) {
    int n = blockIdx.x * blockDim.x + threadIdx.x;
    if (n < NN) atomicAdd(&g_cnt[batch[n]], 1.0f);
}

__global__ void k_state() {
    int b = threadIdx.x;
    if (b < BB) {
        float s = g_pool[b] / fmaxf(g_cnt[b], 1.0f);
        g_state2[2 * b]     = s;
        g_state2[2 * b + 1] = s;
        g_pool[b] = 0.0f;
    }
}

__global__ void k_reset() {
    if (threadIdx.x == 0) g_tile_ctr = 0;
}

// ---------------- node GEMM kernel (4 modes) -----------------------------------
// MODE 0: h2 = [sa,h] @ lin1_w^T + b   (X = h input), writes g_h2, zeroes g_agg
// MODE 1: xf = g_h2 @ conv_lin1_w^T,   writes g_xf
// MODE 2: h  = g_h2 + ssp(g_agg @ conv_lin2_w^T + b), writes g_hbuf (+pool)
// MODE 3: out = g_hbuf @ out_w^T + b,  writes Yext (d_out)
#define NODE_SMEM_FLOATS (17152 + TILE * PAD)
#define NODE_SMEM_BYTES  (NODE_SMEM_FLOATS * 4)

template <int MODE>
__global__ void __launch_bounds__(NTHREADS, 1)
node_gemm(const float* __restrict__ Xext, const float* __restrict__ W,
          const float* __restrict__ bias, const int* __restrict__ batch,
          float* __restrict__ Yext, int do_pool) {
    extern __shared__ float sm[];
    float* sW    = sm;            // 16384
    float* sb    = sm + 16384;    // 128
    float* sw0   = sm + 16512;    // 128
    float* sw1   = sm + 16640;    // 128
    float* spool = sm + 16768;    // 128
    float* ssa0  = sm + 16896;    // 128
    float* ssa1  = sm + 17024;    // 128
    float* sX    = sm + 17152;    // 128*PAD

    const int tid = threadIdx.x;
    const int n0  = blockIdx.x * TILE;

    const float* X;
    float* Y;
    float* aux = 0;
    if (MODE == 0)      { X = Xext ? Xext : g_hbuf; Y = g_h2;   aux = g_agg; }
    else if (MODE == 1) { X = g_h2;                 Y = g_xf; }
    else if (MODE == 2) { X = g_agg;                Y = g_hbuf; aux = g_h2; }
    else                { X = g_hbuf;               Y = Yext; }

    constexpr int ldw  = (MODE == 0) ? 130 : 128;
    constexpr int woff = (MODE == 0) ? 2 : 0;

    for (int i = tid; i < 128 * 128; i += NTHREADS) {
        int f = i >> 7, k = i & 127;
        sW[k * 128 + f] = W[f * ldw + woff + k];
    }
    if (tid < 128) {
        sb[tid] = bias ? bias[tid] : 0.0f;
        spool[tid] = 0.0f;
        if (MODE == 0) {
            sw0[tid] = W[tid * 130];
            sw1[tid] = W[tid * 130 + 1];
            float a0 = 0.0f, a1 = 0.0f;
            int n = n0 + tid;
            if (n < NN) {
                int b = batch[n];
                a0 = g_state2[2 * b];
                a1 = g_state2[2 * b + 1];
            }
            ssa0[tid] = a0;
            ssa1[tid] = a1;
        }
    }
    for (int i = tid; i < TILE * 128; i += NTHREADS) {
        int t = i >> 7, k = i & 127;
        int n = n0 + t;
        sX[k * PAD + t] = (n < NN) ? X[(size_t)n * 128 + k] : 0.0f;
    }
    __syncthreads();

    const int f0 = (tid & 31) * 4;
    const int t0 = (tid >> 5) * 8;

    u64 acc[16];
    if (MODE == 1) {
#pragma unroll
        for (int i = 0; i < 16; i++) acc[i] = 0ull;
    } else {
#pragma unroll
        for (int fi = 0; fi < 4; fi++) {
            u64 bp = pk2(sb[f0 + fi]);
            acc[0 * 4 + fi] = bp;
            acc[1 * 4 + fi] = bp;
            acc[2 * 4 + fi] = bp;
            acc[3 * 4 + fi] = bp;
        }
    }

    if (MODE == 0) {
        ulonglong2 Sa = *(const ulonglong2*)&ssa0[t0];
        ulonglong2 Sb = *(const ulonglong2*)&ssa0[t0 + 4];
        ulonglong2 Ta = *(const ulonglong2*)&ssa1[t0];
        ulonglong2 Tb = *(const ulonglong2*)&ssa1[t0 + 4];
#pragma unroll
        for (int fi = 0; fi < 4; fi++) {
            u64 w0d = pk2(sw0[f0 + fi]);
            u64 w1d = pk2(sw1[f0 + fi]);
            FMA2(acc[0 * 4 + fi], Sa.x, w0d);
            FMA2(acc[1 * 4 + fi], Sa.y, w0d);
            FMA2(acc[2 * 4 + fi], Sb.x, w0d);
            FMA2(acc[3 * 4 + fi], Sb.y, w0d);
            FMA2(acc[0 * 4 + fi], Ta.x, w1d);
            FMA2(acc[1 * 4 + fi], Ta.y, w1d);
            FMA2(acc[2 * 4 + fi], Tb.x, w1d);
            FMA2(acc[3 * 4 + fi], Tb.y, w1d);
        }
    }

    gemm_tile_p<128, PAD>(sW, sX, f0, t0, acc);

#pragma unroll
    for (int tp = 0; tp < 4; tp++) {
        float2 p0 = upk(acc[tp * 4 + 0]);
        float2 p1 = upk(acc[tp * 4 + 1]);
        float2 p2 = upk(acc[tp * 4 + 2]);
        float2 p3 = upk(acc[tp * 4 + 3]);
        float4 v[2];
        v[0] = make_float4(p0.x, p1.x, p2.x, p3.x);
        v[1] = make_float4(p0.y, p1.y, p2.y, p3.y);
#pragma unroll
        for (int hh = 0; hh < 2; hh++) {
            int t = t0 + 2 * tp + hh;
            int n = n0 + t;
            if (n >= NN) continue;
            size_t off = (size_t)n * 128 + f0;
            if (MODE == 0) {
                *(float4*)&Y[off]   = v[hh];
                *(float4*)&aux[off] = make_float4(0.f, 0.f, 0.f, 0.f);
            } else if (MODE == 2) {
                float4 h2v = *(const float4*)&aux[off];
                float4 o;
                o.x = h2v.x + ssp(v[hh].x);
                o.y = h2v.y + ssp(v[hh].y);
                o.z = h2v.z + ssp(v[hh].z);
                o.w = h2v.w + ssp(v[hh].w);
                *(float4*)&Y[off] = o;
                if (do_pool) atomicAdd(&spool[t], o.x + o.y + o.z + o.w);
            } else {
                *(float4*)&Y[off] = v[hh];
            }
        }
    }

    if (MODE == 2 && do_pool) {
        __syncthreads();
        if (tid < TILE) {
            int n = n0 + tid;
            if (n < NN) atomicAdd(&g_pool[batch[n]], spool[tid]);
        }
    }
}

// ---------------- fused edge kernel --------------------------------------------
// Per 128-edge tile: z = ssp(ea @ W1^T + b1); eh = z @ W2^T + b2;
// msg = eh * C * xf[src]; vector-red into agg[dst]. Persistent + work stealing.
#define EDGE_SMEM_FLOATS (30024 + 128 * PAD)
#define EDGE_SMEM_BYTES  (EDGE_SMEM_FLOATS * 4)

__global__ void __launch_bounds__(NTHREADS, 1)
edge_kernel(const float* __restrict__ ea, const float* __restrict__ ew,
            const int* __restrict__ eidx,
            const float* __restrict__ W1, const float* __restrict__ b1,
            const float* __restrict__ W2, const float* __restrict__ b2) {
    extern __shared__ float sm[];
    float* sW1 = sm;                   // 50*128 = 6400
    float* sb1 = sm + 6400;            // 128
    float* sW2 = sm + 6528;            // 16384
    float* sb2 = sm + 22912;           // 128
    float* sC  = sm + 23040;           // 128
    int* sSrc  = (int*)(sm + 23168);   // 128
    int* sDst  = (int*)(sm + 23296);   // 128
    float* sEA = sm + 23424;           // 50*PAD = 6600
    float* sZ  = sm + 30024;           // 128*PAD
    __shared__ int s_tile;

    const int tid = threadIdx.x;

    for (int i = tid; i < 128 * 50; i += NTHREADS) {
        int f = i / 50, k = i - f * 50;
        sW1[k * 128 + f] = W1[i];
    }
    for (int i = tid; i < 128 * 128; i += NTHREADS) {
        int f = i >> 7, k = i & 127;
        sW2[k * 128 + f] = W2[i];
    }
    if (tid < 128) {
        sb1[tid] = b1[tid];
        sb2[tid] = b2[tid];
    }

    const int f0 = (tid & 31) * 4;
    const int t0 = (tid >> 5) * 8;

    for (;;) {
        __syncthreads();
        if (tid == 0) s_tile = atomicAdd(&g_tile_ctr, 1);
        __syncthreads();
        const int tile = s_tile;
        if (tile >= NT_EDGE) break;
        const int e0 = tile * TILE;

        for (int i = tid; i < TILE * 50; i += NTHREADS) {
            int t = i / 50, k = i - t * 50;
            sEA[k * PAD + t] = ea[(size_t)(e0 + t) * 50 + k];
        }
        if (tid < TILE) {
            int e = e0 + tid;
            sC[tid]  = 0.5f * (__cosf(ew[e] * 0.62831853071795864769f) + 1.0f);
            sSrc[tid] = eidx[e];
            sDst[tid] = eidx[EE + e];
        }
        __syncthreads();

        // prefetch xf[src] gathers early (consumed after stage 2)
        float4 xg[8];
#pragma unroll
        for (int j = 0; j < 8; j++)
            xg[j] = *(const float4*)&g_xf[(size_t)sSrc[t0 + j] * 128 + f0];

        // stage 1: z = ssp(ea @ W1^T + b1), stored [k][t]
        {
            u64 acc[16];
#pragma unroll
            for (int fi = 0; fi < 4; fi++) {
                u64 bp = pk2(sb1[f0 + fi]);
                acc[0 * 4 + fi] = bp;
                acc[1 * 4 + fi] = bp;
                acc[2 * 4 + fi] = bp;
                acc[3 * 4 + fi] = bp;
            }
            gemm_tile_p<50, PAD>(sW1, sEA, f0, t0, acc);
#pragma unroll
            for (int fi = 0; fi < 4; fi++) {
#pragma unroll
                for (int tp = 0; tp < 4; tp++) {
                    float2 p = upk(acc[tp * 4 + fi]);
                    p.x = ssp(p.x);
                    p.y = ssp(p.y);
                    *(float2*)&sZ[(f0 + fi) * PAD + t0 + 2 * tp] = p;
                }
            }
        }
        __syncthreads();

        // stage 2: eh = z @ W2^T + b2; msg = eh*C*xf[src]; vector-red to agg[dst]
        {
            u64 acc[16];
#pragma unroll
            for (int fi = 0; fi < 4; fi++) {
                u64 bp = pk2(sb2[f0 + fi]);
                acc[0 * 4 + fi] = bp;
                acc[1 * 4 + fi] = bp;
                acc[2 * 4 + fi] = bp;
                acc[3 * 4 + fi] = bp;
            }
            gemm_tile_p<128, PAD>(sW2, sZ, f0, t0, acc);
#pragma unroll
            for (int tp = 0; tp < 4; tp++) {
                float2 p0 = upk(acc[tp * 4 + 0]);
                float2 p1 = upk(acc[tp * 4 + 1]);
                float2 p2 = upk(acc[tp * 4 + 2]);
                float2 p3 = upk(acc[tp * 4 + 3]);
                float4 v[2];
                v[0] = make_float4(p0.x, p1.x, p2.x, p3.x);
                v[1] = make_float4(p0.y, p1.y, p2.y, p3.y);
#pragma unroll
                for (int hh = 0; hh < 2; hh++) {
                    int j = 2 * tp + hh;
                    int t = t0 + j;
                    float c = sC[t];
                    int d = sDst[t];
                    float4 m;
                    m.x = v[hh].x * c * xg[j].x;
                    m.y = v[hh].y * c * xg[j].y;
                    m.z = v[hh].z * c * xg[j].z;
                    m.w = v[hh].w * c * xg[j].w;
                    float* ap = g_agg + (size_t)d * 128 + f0;
                    asm volatile("red.global.add.v4.f32 [%0], {%1, %2, %3, %4};"
                                 :: "l"(ap), "f"(m.x), "f"(m.y), "f"(m.z), "f"(m.w)
                                 : "memory");
                }
            }
        }
    }
}

// ---------------- launcher -----------------------------------------------------
extern "C" void kernel_launch(void* const* d_in, const int* in_sizes, int n_in,
                              void* d_out, int out_size) {
    const float* h      = (const float*)d_in[0];
    const float* ew     = (const float*)d_in[1];
    const float* ea     = (const float*)d_in[2];
    const float* st     = (const float*)d_in[3];
    const float* lin1w  = (const float*)d_in[4];
    const float* lin1b  = (const float*)d_in[5];
    const float* mw1    = (const float*)d_in[6];
    const float* mb1    = (const float*)d_in[7];
    const float* mw2    = (const float*)d_in[8];
    const float* mb2    = (const float*)d_in[9];
    const float* cl1    = (const float*)d_in[10];
    const float* cl2    = (const float*)d_in[11];
    const float* cl2b   = (const float*)d_in[12];
    const float* outw   = (const float*)d_in[13];
    const float* outb   = (const float*)d_in[14];
    const int* eidx  = (const int*)d_in[15];
    const int* batch = (const int*)d_in[16];
    float* out = (float*)d_out;

    cudaFuncSetAttribute(node_gemm<0>, cudaFuncAttributeMaxDynamicSharedMemorySize, NODE_SMEM_BYTES);
    cudaFuncSetAttribute(node_gemm<1>, cudaFuncAttributeMaxDynamicSharedMemorySize, NODE_SMEM_BYTES);
    cudaFuncSetAttribute(node_gemm<2>, cudaFuncAttributeMaxDynamicSharedMemorySize, NODE_SMEM_BYTES);
    cudaFuncSetAttribute(node_gemm<3>, cudaFuncAttributeMaxDynamicSharedMemorySize, NODE_SMEM_BYTES);
    cudaFuncSetAttribute(edge_kernel,  cudaFuncAttributeMaxDynamicSharedMemorySize, EDGE_SMEM_BYTES);

    k_init<<<1, 256>>>(st);
    k_count<<<(NN + 255) / 256, 256>>>(batch);

    for (int i = 0; i < 2; i++) {
        const float* hin = (i == 0) ? h : (const float*)0;  // null => g_hbuf
        node_gemm<0><<<NB_NODE, NTHREADS, NODE_SMEM_BYTES>>>(
            hin, lin1w + i * 128 * 130, lin1b + i * 128, batch, (float*)0, 0);
        node_gemm<1><<<NB_NODE, NTHREADS, NODE_SMEM_BYTES>>>(
            (const float*)0, cl1 + i * 128 * 128, (const float*)0, batch, (float*)0, 0);
        k_reset<<<1, 32>>>();
        edge_kernel<<<EDGE_BLOCKS, NTHREADS, EDGE_SMEM_BYTES>>>(
            ea, ew, eidx, mw1 + i * 128 * 50, mb1 + i * 128,
            mw2 + i * 128 * 128, mb2 + i * 128);
        node_gemm<2><<<NB_NODE, NTHREADS, NODE_SMEM_BYTES>>>(
            (const float*)0, cl2 + i * 128 * 128, cl2b + i * 128, batch, (float*)0,
            (i == 0) ? 1 : 0);
        if (i == 0) k_state<<<1, 256>>>();
    }
    node_gemm<3><<<NB_NODE, NTHREADS, NODE_SMEM_BYTES>>>(
        (const float*)0, outw, outb, batch, out, 0);
}